// round 2
// baseline (speedup 1.0000x reference)
#include <cuda_runtime.h>

#define T 4096
#define H 4096
#define K 8
#define E 64
#define TK (T*K)        // 32768 slots

// Scratch (no cudaMalloc allowed)
__device__ int g_dest[TK];           // final destination slot of source slot s

// ---------------------------------------------------------------------------
// Kernel 1 (the whole sort): 64 blocks, one per expert e; 1024 threads.
// Pass 1: block reduction of (#idx < e)  -> expertbase, (#idx == e) -> tpe.
// Pass 2: stable block-wide scan over (idx == e) in 32 chunks of 1024,
//         writing g_dest[s] = expertbase + running_rank for matching slots.
// idx is 128 KB -> L2-resident; total extra reads ~16 MB, all L2 hits.
// ---------------------------------------------------------------------------
__global__ void __launch_bounds__(1024) k_sort(const int* __restrict__ idx,
                                               float* __restrict__ tpe) {
    const int e    = blockIdx.x;
    const int tid  = threadIdx.x;
    const int w    = tid >> 5;
    const int lane = tid & 31;

    __shared__ int sred[32];
    __shared__ int swarp[32];

    // ---- Pass 1: count idx<e and idx==e over all TK slots ----
    int lt = 0, eq = 0;
    #pragma unroll
    for (int c = 0; c < TK / 1024; c++) {
        const int v = idx[c * 1024 + tid];
        lt += (v < e);
        eq += (v == e);
    }
    // pack (lt in high 16 impossible—counts can reach 32768; use two reductions)
    // warp reduce
    #pragma unroll
    for (int o = 16; o > 0; o >>= 1) {
        lt += __shfl_down_sync(0xffffffffu, lt, o);
        eq += __shfl_down_sync(0xffffffffu, eq, o);
    }
    if (lane == 0) sred[w] = lt;
    __syncthreads();
    if (w == 0) {
        int v = sred[lane];
        #pragma unroll
        for (int o = 16; o > 0; o >>= 1) v += __shfl_down_sync(0xffffffffu, v, o);
        if (lane == 0) sred[0] = v;     // expertbase
    }
    __syncthreads();
    const int expertbase = sred[0];
    __syncthreads();
    if (lane == 0) sred[w] = eq;
    __syncthreads();
    if (w == 0 && tpe) {
        int v = sred[lane];
        #pragma unroll
        for (int o = 16; o > 0; o >>= 1) v += __shfl_down_sync(0xffffffffu, v, o);
        if (lane == 0) tpe[e] = (float)v;
    }

    // ---- Pass 2: stable scan of matches, chunk by chunk ----
    int running = expertbase;
    #pragma unroll
    for (int c = 0; c < TK / 1024; c++) {
        const int s = c * 1024 + tid;
        const bool m = (idx[s] == e);
        const unsigned bal = __ballot_sync(0xffffffffu, m);
        const int rank_in_warp = __popc(bal & ((1u << lane) - 1u));
        if (lane == 0) swarp[w] = __popc(bal);
        __syncthreads();
        // exclusive scan over 32 warp counts (warp 0)
        if (w == 0) {
            int v = swarp[lane];
            int orig = v;
            #pragma unroll
            for (int o = 1; o < 32; o <<= 1) {
                int n = __shfl_up_sync(0xffffffffu, v, o);
                if (lane >= o) v += n;
            }
            swarp[lane] = v - orig;          // exclusive
            if (lane == 31) sred[1] = v;     // chunk total
        }
        __syncthreads();
        if (m) g_dest[s] = running + swarp[w] + rank_in_warp;
        running += sred[1];
        __syncthreads();
    }
}

// ---------------------------------------------------------------------------
// Kernel 2: the bandwidth kernel. One block per token. Read the 16KB row
// ONCE into registers, write 8 dispatched copies + 1 weighted combined row.
// dest/weights are uniform per block -> broadcast __ldg, no smem, no barriers.
// ---------------------------------------------------------------------------
__global__ void __launch_bounds__(256) k_main(const float4* __restrict__ x4,
                                              const float*  __restrict__ wts,
                                              float4* __restrict__ comb4,
                                              float4* __restrict__ disp4) {
    const int t   = blockIdx.x;
    const int tid = threadIdx.x;
    const int ROW4 = H / 4;          // 1024 float4 per row

    // Kick off the big row loads immediately.
    float4 v[4];
    #pragma unroll
    for (int i = 0; i < 4; i++)
        v[i] = __ldg(&x4[(size_t)t * ROW4 + tid + i * 256]);

    // Uniform per-block metadata via broadcast loads (1 transaction/warp).
    int dst[K];
    #pragma unroll
    for (int k = 0; k < K; k++) dst[k] = __ldg(&g_dest[t * K + k]);
    float ws = 0.f;
    #pragma unroll
    for (int k = 0; k < K; k++) ws += __ldg(&wts[t * K + k]);

    if (comb4) {
        #pragma unroll
        for (int i = 0; i < 4; i++) {
            float4 o = make_float4(v[i].x * ws, v[i].y * ws, v[i].z * ws, v[i].w * ws);
            __stcs(&comb4[(size_t)t * ROW4 + tid + i * 256], o);
        }
    }
    if (disp4) {
        #pragma unroll
        for (int k = 0; k < K; k++) {
            const size_t base = (size_t)dst[k] * ROW4;
            #pragma unroll
            for (int i = 0; i < 4; i++)
                __stcs(&disp4[base + tid + i * 256], v[i]);
        }
    }
}

// ---------------------------------------------------------------------------
extern "C" void kernel_launch(void* const* d_in, const int* in_sizes, int n_in,
                              void* d_out, int out_size) {
    const float* x   = (const float*)d_in[0];
    const int*   idx = (const int*)  d_in[1];
    const float* w   = (const float*)d_in[2];
    float* out = (float*)d_out;

    const long long TH  = (long long)T * H;          // 16,777,216
    const long long TKH = (long long)TK * H;         // 134,217,728
    const long long os  = (long long)out_size;

    float* comb = nullptr;
    float* disp = nullptr;
    float* tpe  = nullptr;

    if (os >= TH + TKH) {
        comb = out;
        disp = out + TH;
        if (os >= TH + TKH + E) tpe = out + TH + TKH;
    } else if (os == TKH) {
        disp = out;                                  // dispatched-only layout
    } else {
        comb = out;                                  // combined-only layout
    }

    k_sort<<<E, 1024>>>(idx, tpe);
    k_main<<<T, 256>>>((const float4*)x, w, (float4*)comb, (float4*)disp);
}

// round 3
// speedup vs baseline: 1.0492x; 1.0492x over previous
#include <cuda_runtime.h>

#define T 4096
#define H 4096
#define K 8
#define E 64
#define TK (T*K)        // 32768 slots
#define NBLK 32         // sort blocks of 1024 slots each

// Scratch (no cudaMalloc allowed)
__device__ int g_rank[TK];           // stable rank within (block, expert)
__device__ int g_blockcount[NBLK*E]; // per-block per-expert counts
__device__ int g_blockbase[NBLK*E];  // exclusive prefix over blocks, per expert
__device__ int g_expertbase[E];      // exclusive prefix over experts

// ---------------------------------------------------------------------------
// Kernel 1: per-block stable ranks + per-block expert histograms.
// 32 blocks x 1024 threads; slot s = b*1024 + tid. Warp-level match gives
// in-warp stable rank; a 64-thread scan over the 32 warp histograms gives
// the warp base within the block.
// ---------------------------------------------------------------------------
__global__ void __launch_bounds__(1024) k_rank_hist(const int* __restrict__ idx) {
    __shared__ int whist[32 * E];    // [warp][expert]
    const int tid  = threadIdx.x;
    const int b    = blockIdx.x;
    const int w    = tid >> 5;
    const int lane = tid & 31;

    for (int i = tid; i < 32 * E; i += 1024) whist[i] = 0;
    __syncthreads();

    const int s = b * 1024 + tid;
    const int e = idx[s];

    unsigned mask = __match_any_sync(0xffffffffu, e);
    const int rank_in_warp = __popc(mask & ((1u << lane) - 1u));
    const int leader = __ffs(mask) - 1;
    if (lane == leader) whist[w * E + e] = __popc(mask);
    __syncthreads();

    // Exclusive scan across warps for each expert bin (threads 0..63)
    if (tid < E) {
        int run = 0;
        #pragma unroll
        for (int ww = 0; ww < 32; ww++) {
            int c = whist[ww * E + tid];
            whist[ww * E + tid] = run;
            run += c;
        }
        g_blockcount[b * E + tid] = run;   // block total for this expert
    }
    __syncthreads();

    g_rank[s] = whist[w * E + e] + rank_in_warp;
}

// ---------------------------------------------------------------------------
// Kernel 2: single block, 64 threads. Per-expert exclusive scan over blocks,
// then exclusive scan over experts. Also emits tokens_per_expert (as float).
// ---------------------------------------------------------------------------
__global__ void k_scan(float* __restrict__ tpe_out) {
    const int e = threadIdx.x;   // 0..63
    int run = 0;
    #pragma unroll
    for (int b = 0; b < NBLK; b++) {
        int c = g_blockcount[b * E + e];
        g_blockbase[b * E + e] = run;
        run += c;
    }
    __shared__ int tot[E];
    __shared__ int base[E];
    tot[e] = run;
    __syncthreads();
    if (e == 0) {
        int acc = 0;
        #pragma unroll
        for (int i = 0; i < E; i++) { base[i] = acc; acc += tot[i]; }
    }
    __syncthreads();
    g_expertbase[e] = base[e];
    if (tpe_out) tpe_out[e] = (float)tot[e];
}

// ---------------------------------------------------------------------------
// Kernel 3: the bandwidth kernel, with destination reconstruction fused in.
// One block per token. Read the 16KB row ONCE into registers, write 8
// dispatched copies + 1 weighted combined row. All metadata loads are
// uniform per block -> broadcast __ldg (1 transaction/warp, L1/L2 hits).
// ---------------------------------------------------------------------------
__global__ void __launch_bounds__(256) k_main(const float4* __restrict__ x4,
                                              const float*  __restrict__ wts,
                                              const int*    __restrict__ idx,
                                              float4* __restrict__ comb4,
                                              float4* __restrict__ disp4) {
    const int t   = blockIdx.x;
    const int tid = threadIdx.x;
    const int ROW4 = H / 4;          // 1024 float4 per row

    // Kick off the big row loads immediately.
    float4 v[4];
    #pragma unroll
    for (int i = 0; i < 4; i++)
        v[i] = __ldg(&x4[(size_t)t * ROW4 + tid + i * 256]);

    // Reconstruct the 8 destination slots inline (uniform per block).
    int dst[K];
    #pragma unroll
    for (int k = 0; k < K; k++) {
        const int s = t * K + k;
        const int b = s >> 10;                 // which sort block
        const int e = __ldg(&idx[s]);
        dst[k] = __ldg(&g_expertbase[e]) + __ldg(&g_blockbase[b * E + e])
               + __ldg(&g_rank[s]);
    }
    float ws = 0.f;
    #pragma unroll
    for (int k = 0; k < K; k++) ws += __ldg(&wts[t * K + k]);

    if (comb4) {
        #pragma unroll
        for (int i = 0; i < 4; i++) {
            float4 o = make_float4(v[i].x * ws, v[i].y * ws, v[i].z * ws, v[i].w * ws);
            __stcs(&comb4[(size_t)t * ROW4 + tid + i * 256], o);
        }
    }
    if (disp4) {
        #pragma unroll
        for (int k = 0; k < K; k++) {
            const size_t base = (size_t)dst[k] * ROW4;
            #pragma unroll
            for (int i = 0; i < 4; i++)
                __stcs(&disp4[base + tid + i * 256], v[i]);
        }
    }
}

// ---------------------------------------------------------------------------
extern "C" void kernel_launch(void* const* d_in, const int* in_sizes, int n_in,
                              void* d_out, int out_size) {
    const float* x   = (const float*)d_in[0];
    const int*   idx = (const int*)  d_in[1];
    const float* w   = (const float*)d_in[2];
    float* out = (float*)d_out;

    const long long TH  = (long long)T * H;          // 16,777,216
    const long long TKH = (long long)TK * H;         // 134,217,728
    const long long os  = (long long)out_size;

    float* comb = nullptr;
    float* disp = nullptr;
    float* tpe  = nullptr;

    if (os >= TH + TKH) {
        comb = out;
        disp = out + TH;
        if (os >= TH + TKH + E) tpe = out + TH + TKH;
    } else if (os == TKH) {
        disp = out;                                  // dispatched-only layout
    } else {
        comb = out;                                  // combined-only layout
    }

    k_rank_hist<<<NBLK, 1024>>>(idx);
    k_scan<<<1, 64>>>(tpe);
    k_main<<<T, 256>>>((const float4*)x, w, idx, (float4*)comb, (float4*)disp);
}

// round 4
// speedup vs baseline: 1.0550x; 1.0056x over previous
#include <cuda_runtime.h>

#define T 4096
#define H 4096
#define K 8
#define E 64
#define TK (T*K)            // 32768 slots
#define SORTB 64            // sort blocks (blocks 0..63)
#define NTOT (T + SORTB)    // total grid

// Scratch (no cudaMalloc allowed)
__device__ int g_rank[TK];            // stable rank within (sortblock, expert)
__device__ int g_blockcount[SORTB*E];
__device__ int g_blockbase[SORTB*E];
__device__ int g_expertbase[E];
__device__ int g_arrive;              // monotonic across replays; use %SORTB
__device__ int g_done;                // monotonic across replays; use %NTOT
__device__ int g_flag;                // 0 at launch start; 1 = sort done; reset by last block

// ---------------------------------------------------------------------------
// One fused kernel. Blocks [0,64): counting sort of the 32768 (token,k) slots
// over 64 experts. Blocks [64,4160): per-token bandwidth work. Token blocks
// overlap their x-row loads + combined writes with the sort, then poll g_flag
// before the dispatched scatter.
// ---------------------------------------------------------------------------
__global__ void __launch_bounds__(256) k_fused(const float4* __restrict__ x4,
                                               const float*  __restrict__ wts,
                                               const int*    __restrict__ idx,
                                               float4* __restrict__ comb4,
                                               float4* __restrict__ disp4,
                                               float*  __restrict__ tpe) {
    const int tid = threadIdx.x;

    if (blockIdx.x < SORTB) {
        // ================= SORT ROLE =================
        __shared__ int whist[8 * E];   // [warp][expert] prefix workspace
        __shared__ int off[E];         // running per-expert offset across chunks
        __shared__ int s_last;
        const int b    = blockIdx.x;
        const int w    = tid >> 5;
        const int lane = tid & 31;

        if (tid < E) off[tid] = 0;

        #pragma unroll
        for (int c = 0; c < 2; c++) {            // 2 chunks of 256 slots
            whist[tid] = 0; whist[tid + 256] = 0;
            __syncthreads();
            const int s = b * 512 + c * 256 + tid;
            const int e = __ldg(&idx[s]);
            unsigned mask = __match_any_sync(0xffffffffu, e);
            const int riw = __popc(mask & ((1u << lane) - 1u));
            if ((__ffs(mask) - 1) == lane) whist[w * E + e] = __popc(mask);
            __syncthreads();
            if (tid < E) {                       // scan 8 warp counts, add chunk offset
                int run = 0;
                #pragma unroll
                for (int ww = 0; ww < 8; ww++) {
                    int cc = whist[ww * E + tid];
                    whist[ww * E + tid] = off[tid] + run;
                    run += cc;
                }
                off[tid] += run;
            }
            __syncthreads();
            g_rank[s] = whist[w * E + e] + riw;
            __syncthreads();                     // protect whist/off for next chunk
        }
        if (tid < E) g_blockcount[b * E + tid] = off[tid];
        __threadfence();
        if (tid == 0) {
            int ticket = atomicAdd(&g_arrive, 1);
            s_last = ((ticket & (SORTB - 1)) == (SORTB - 1));
        }
        __syncthreads();
        if (s_last) {
            // Last-to-arrive block: cross-block + cross-expert scans.
            __threadfence();
            __shared__ int tot[E];
            __shared__ int base[E];
            if (tid < E) {
                int run = 0;
                #pragma unroll
                for (int bb = 0; bb < SORTB; bb++) {
                    int cc = g_blockcount[bb * E + tid];
                    g_blockbase[bb * E + tid] = run;
                    run += cc;
                }
                tot[tid] = run;
            }
            __syncthreads();
            if (tid == 0) {
                int acc = 0;
                #pragma unroll
                for (int i = 0; i < E; i++) { base[i] = acc; acc += tot[i]; }
            }
            __syncthreads();
            if (tid < E) {
                g_expertbase[tid] = base[tid];
                if (tpe) tpe[tid] = (float)tot[tid];
            }
            __threadfence();
            if (tid == 0) atomicExch(&g_flag, 1);
        }
    } else {
        // ================= TOKEN ROLE =================
        const int t = blockIdx.x - SORTB;
        const int ROW4 = H / 4;                  // 1024 float4 per row

        float4 v[4];
        #pragma unroll
        for (int i = 0; i < 4; i++)
            v[i] = __ldg(&x4[(size_t)t * ROW4 + tid + i * 256]);

        float ws = 0.f;
        #pragma unroll
        for (int k = 0; k < K; k++) ws += __ldg(&wts[t * K + k]);

        if (comb4) {
            #pragma unroll
            for (int i = 0; i < 4; i++) {
                float4 o = make_float4(v[i].x * ws, v[i].y * ws, v[i].z * ws, v[i].w * ws);
                __stcs(&comb4[(size_t)t * ROW4 + tid + i * 256], o);
            }
        }
        if (disp4) {
            // Wait for sort completion (one poller per block, backoff).
            if (tid == 0) {
                while (*((volatile int*)&g_flag) == 0) __nanosleep(128);
            }
            __syncthreads();
            __threadfence();

            int dst[K];
            #pragma unroll
            for (int k = 0; k < K; k++) {
                const int s  = t * K + k;
                const int bb = s >> 9;           // 512 slots per sort block
                const int e  = idx[s];
                dst[k] = g_expertbase[e] + g_blockbase[bb * E + e] + g_rank[s];
            }
            #pragma unroll
            for (int k = 0; k < K; k++) {
                const size_t basep = (size_t)dst[k] * ROW4;
                #pragma unroll
                for (int i = 0; i < 4; i++)
                    __stcs(&disp4[basep + tid + i * 256], v[i]);
            }
        }
    }

    // Epilogue: globally-last block resets g_flag for the next graph replay.
    __syncthreads();
    if (threadIdx.x == 0) {
        __threadfence();
        int d = atomicAdd(&g_done, 1);
        if ((d % NTOT) == (NTOT - 1)) atomicExch(&g_flag, 0);
    }
}

// ---------------------------------------------------------------------------
extern "C" void kernel_launch(void* const* d_in, const int* in_sizes, int n_in,
                              void* d_out, int out_size) {
    const float* x   = (const float*)d_in[0];
    const int*   idx = (const int*)  d_in[1];
    const float* w   = (const float*)d_in[2];
    float* out = (float*)d_out;

    const long long TH  = (long long)T * H;          // 16,777,216
    const long long TKH = (long long)TK * H;         // 134,217,728
    const long long os  = (long long)out_size;

    float* comb = nullptr;
    float* disp = nullptr;
    float* tpe  = nullptr;

    if (os >= TH + TKH) {
        comb = out;
        disp = out + TH;
        if (os >= TH + TKH + E) tpe = out + TH + TKH;
    } else if (os == TKH) {
        disp = out;                                  // dispatched-only layout
    } else {
        comb = out;                                  // combined-only layout
    }

    k_fused<<<NTOT, 256>>>((const float4*)x, w, idx,
                           (float4*)comb, (float4*)disp, tpe);
}